// round 7
// baseline (speedup 1.0000x reference)
#include <cuda_runtime.h>
#include <cmath>

// ---------------------------------------------------------------------------
// CTLNN persistent kernel, round 7.
// 128 CTAs x 512 threads. Column-partitioned fp32 weights in SMEM.
// Two time-staggered row-streams (rows 0-31 / 32-63), each with its own
// split arrive/wait grid barrier; between arrive and wait runs a full phase
// of the other stream, hiding barrier + L2 latency. Per stream, thread
// (r:32, c2:2, kpart:8) computes 2 columns over a K/8 slice. LayerNorm folded
// into phase A (gamma into Wm h-rows, rstd into staged v, beta/mu constants).
// cp.async double-buffered staging, FFMA2 inner loops. 3 barriers/stream/step.
// ---------------------------------------------------------------------------

namespace {
constexpr int Tt   = 1024;
constexpr int DIN  = 256;
constexpr int Hh   = 512;
constexpr int NCTA = 128;
constexpr int NTHR = 512;
constexpr float DTc  = 0.01f;
constexpr float EPSc = 1e-5f;

// SMEM float offsets
constexpr int OFF_WMX   = 0;        // 8 x 256 (x-rows of Wm) [c8][k]
constexpr int OFF_WMV   = 2048;     // 8 x 512 (h-rows, gamma-folded)
constexpr int OFF_WT    = 6144;     // 4 x 512
constexpr int OFF_WF1   = 8192;
constexpr int OFF_WF2   = 10240;
constexpr int OFF_STAGE = 12288;    // 4 buffers x 2048 float4 (32KB each)
constexpr int OFF_RED   = 45056;    // 512 x 4 floats
constexpr int OFF_B     = 47104;    // 48 consts
constexpr int OFF_RSTD  = 47152;    // 64 (both streams)
constexpr int SMEM_FLOATS = 47216;  // ~184.4 KB
// OFF_B: [0..3] bm_g [4..7] bm_core [8..11] bt [12..15] bf1 [16..19] bf2
//        [20..23] gamma_c [24..27] beta_c [28..35] Bsum [36..43] Gsum
}

// Cross-CTA state
__device__ unsigned g_barS[2];
__device__ float g_rs[128], g_rq[128];   // [s][par][32] -> s*64+par*32+r
__device__ float g_v[64 * Hh];
__device__ float g_core[64 * Hh];
__device__ float g_z[64 * Hh];
__device__ float g_a1[64 * Hh];

__global__ void ctlnn_reset() {
    int i = blockIdx.x * blockDim.x + threadIdx.x;
    if (i < 2) g_barS[i] = 0u;
    if (i < 128) { g_rs[i] = 0.f; g_rq[i] = 0.f; }
    for (int k = i; k < 64 * Hh; k += gridDim.x * blockDim.x) g_v[k] = 0.f;
}

// ---- helpers --------------------------------------------------------------
__device__ __forceinline__ void cp16(float4* dst, const void* src) {
    unsigned s = (unsigned)__cvta_generic_to_shared(dst);
    asm volatile("cp.async.cg.shared.global [%0], [%1], 16;" :: "r"(s), "l"(src));
}
__device__ __forceinline__ void cp_commit() {
    asm volatile("cp.async.commit_group;" ::: "memory");
}
template <int N>
__device__ __forceinline__ void cp_wait() {
    asm volatile("cp.async.wait_group %0;" :: "n"(N) : "memory");
}
__device__ __forceinline__ void fma2(unsigned long long& d,
                                     unsigned long long a, unsigned long long b) {
    asm volatile("fma.rn.f32x2 %0, %1, %2, %3;" : "=l"(d) : "l"(a), "l"(b), "l"(d));
}
__device__ __forceinline__ unsigned long long mul2(unsigned long long a,
                                                   unsigned long long b) {
    unsigned long long d;
    asm("mul.rn.f32x2 %0, %1, %2;" : "=l"(d) : "l"(a), "l"(b));
    return d;
}
__device__ __forceinline__ float hsum(unsigned long long u) {
    float lo, hi;
    asm("mov.b64 {%0,%1}, %2;" : "=f"(lo), "=f"(hi) : "l"(u));
    return lo + hi;
}

__device__ __forceinline__ void bar_arrive(int s) {
    __threadfence();
    __syncthreads();
    if (threadIdx.x == 0) atomicAdd(&g_barS[s], 1u);
}
__device__ __forceinline__ void bar_wait(int s, unsigned target) {
    if (threadIdx.x == 0) {
        unsigned v;
        do {
            asm volatile("ld.global.acquire.gpu.u32 %0, [%1];"
                         : "=r"(v) : "l"(&g_barS[s]));
        } while (v < target);
    }
    __syncthreads();
}

// Stage one 32-row x 64-granule(16B) chunk into SMEM with XOR swizzle.
__device__ __forceinline__ void stage32(float4* __restrict__ dst,
                                        const char* __restrict__ gbase,
                                        size_t rstrideB, int rs0, int kk) {
#pragma unroll
    for (int i = 0; i < 4; ++i) {
        int rs = rs0 + i * 8;
        cp16(dst + rs * 64 + (kk ^ (rs & 7)),
             gbase + (size_t)rs * rstrideB + kk * 16);
    }
    cp_commit();
}

__global__ void __launch_bounds__(NTHR, 1)
ctlnn_main(const float* __restrict__ x,
           const float* __restrict__ Wm,  const float* __restrict__ bm,
           const float* __restrict__ Wf1, const float* __restrict__ bf1,
           const float* __restrict__ Wf2, const float* __restrict__ bf2,
           const float* __restrict__ Wt,  const float* __restrict__ bt,
           const float* __restrict__ gamma, const float* __restrict__ beta,
           float* __restrict__ out) {
    extern __shared__ __align__(16) float sm[];
    const int tid = threadIdx.x;
    const int bid = blockIdx.x;

    // ---- one-time weight slice load ----
    for (int idx = tid; idx < 8 * 256; idx += NTHR) {          // Wm x-rows
        int c8 = idx >> 8, k = idx & 255;
        int srccol = (c8 < 4) ? (bid * 4 + c8) : (512 + bid * 4 + (c8 - 4));
        sm[OFF_WMX + idx] = Wm[k * 1024 + srccol];
    }
    for (int idx = tid; idx < 8 * 512; idx += NTHR) {          // Wm h-rows *gamma
        int c8 = idx >> 9, k = idx & 511;
        int srccol = (c8 < 4) ? (bid * 4 + c8) : (512 + bid * 4 + (c8 - 4));
        sm[OFF_WMV + idx] = Wm[(256 + k) * 1024 + srccol] * gamma[k];
    }
    for (int idx = tid; idx < 4 * 512; idx += NTHR) {
        int c4 = idx >> 9, k = idx & 511;
        int col0 = bid * 4 + c4;
        sm[OFF_WT  + idx] = Wt [k * 512 + col0];
        sm[OFF_WF1 + idx] = Wf1[k * 512 + col0];
        sm[OFF_WF2 + idx] = Wf2[k * 512 + col0];
    }
    if (tid < 4) {
        int col0 = bid * 4 + tid;
        sm[OFF_B +  0 + tid] = bm[col0];
        sm[OFF_B +  4 + tid] = bm[512 + col0];
        sm[OFF_B +  8 + tid] = bt[col0];
        sm[OFF_B + 12 + tid] = bf1[col0];
        sm[OFF_B + 16 + tid] = bf2[col0];
        sm[OFF_B + 20 + tid] = gamma[col0];
        sm[OFF_B + 24 + tid] = beta[col0];
    }
    {   // per-column LN-fold constants
        int w = tid >> 5, lane = tid & 31;
        if (w < 8) {
            int srccol = (w < 4) ? (bid * 4 + w) : (512 + bid * 4 + (w - 4));
            float sb = 0.f, sg = 0.f;
            for (int k = lane; k < 512; k += 32) {
                float wv = Wm[(256 + k) * 1024 + srccol];
                sb += beta[k] * wv;
                sg += gamma[k] * wv;
            }
#pragma unroll
            for (int o = 16; o; o >>= 1) {
                sb += __shfl_xor_sync(~0u, sb, o);
                sg += __shfl_xor_sync(~0u, sg, o);
            }
            if (lane == 0) { sm[OFF_B + 28 + w] = sb; sm[OFF_B + 36 + w] = sg; }
        }
    }
    __syncthreads();

    float4* SB = reinterpret_cast<float4*>(sm + OFF_STAGE);    // 4 x 2048
    float4* red4 = reinterpret_cast<float4*>(sm + OFF_RED);
    float2* red2 = reinterpret_cast<float2*>(sm + OFF_RED);
    const ulonglong2* WMXu = reinterpret_cast<const ulonglong2*>(sm + OFF_WMX);
    const ulonglong2* WMVu = reinterpret_cast<const ulonglong2*>(sm + OFF_WMV);
    const ulonglong2* WTu  = reinterpret_cast<const ulonglong2*>(sm + OFF_WT);
    const ulonglong2* WF1u = reinterpret_cast<const ulonglong2*>(sm + OFF_WF1);
    const ulonglong2* WF2u = reinterpret_cast<const ulonglong2*>(sm + OFF_WF2);

    const int r     = tid & 31;          // row within stream
    const int c2    = (tid >> 5) & 1;    // column pair
    const int kpart = tid >> 6;          // K-eighth
    const int sw    = r & 7;
    const int rs0   = tid >> 6;          // staging row phase
    const int kk    = tid & 63;          // staging granule
    const int cbase = bid * 4;
    const int col0  = 2 * c2;
    const bool owner = (kpart == 0);

    float hprev[2][2] = {{0.f,0.f},{0.f,0.f}};
    float dtT[2][2]   = {{0.f,0.f},{0.f,0.f}};
    float vkeep[2][2] = {{0.f,0.f},{0.f,0.f}};
    unsigned cnt[2] = {0u, 0u};

    // prefetch x(t=0) for both streams: stream s -> SB[2s]
    stage32(SB + 0 * 2048, (const char*)(x + (size_t)0 * Tt * DIN),
            (size_t)Tt * DIN * 4, rs0, kk);
    stage32(SB + 2 * 2048, (const char*)(x + (size_t)32 * Tt * DIN),
            (size_t)Tt * DIN * 4, rs0, kk);
    cp_wait<1>();   // x0 complete; x1 drained by A0's waits

    for (int t = 0; t < Tt; ++t) {
        const int par = t & 1;

        // ======================= PHASE A (both streams) =====================
#pragma unroll
        for (int s = 0; s < 2; ++s) {
            float4* b0 = SB + (2 * s) * 2048;
            float4* b1 = SB + (2 * s + 1) * 2048;
            const char* vbase = (const char*)(g_v + (size_t)s * 32 * Hh);

            bar_wait(s, cnt[s]);                       // D-barrier of prev step
            stage32(b1, vbase, Hh * 4, rs0, kk);       // Va (K 0..255)

            float muv = 0.f, rstdv = 0.f;
            if (owner) {                               // finalize t-1
                if (t > 0) {
                    int pp = (t - 1) & 1;
                    float ssum = __ldcg(&g_rs[s * 64 + pp * 32 + r]);
                    float qsum = __ldcg(&g_rq[s * 64 + pp * 32 + r]);
                    muv = ssum * (1.f / 512.f);
                    float var = qsum * (1.f / 512.f) - muv * muv;
                    rstdv = rsqrtf(var + EPSc);
                    float2 hn;
                    hn.x = (vkeep[s][0] - muv) * rstdv * sm[OFF_B + 20 + col0]
                           + sm[OFF_B + 24 + col0];
                    hn.y = (vkeep[s][1] - muv) * rstdv * sm[OFF_B + 20 + col0 + 1]
                           + sm[OFF_B + 24 + col0 + 1];
                    *reinterpret_cast<float2*>(
                        out + ((size_t)(s * 32 + r) * Tt + (t - 1)) * Hh
                            + cbase + col0) = hn;
                    hprev[s][0] = hn.x; hprev[s][1] = hn.y;
                }
                if (c2 == 0) sm[OFF_RSTD + s * 32 + r] = rstdv;
            }

            unsigned long long ag[2][2] = {}, ac[2][2] = {};
            // x dot (b0, complete by construction)
            {
                const ulonglong2* sp =
                    reinterpret_cast<const ulonglong2*>(b0) + r * 64;
#pragma unroll
                for (int j = 0; j < 8; ++j) {
                    int l = j * 8 + kpart;
                    ulonglong2 a = sp[l ^ sw];
#pragma unroll
                    for (int cc = 0; cc < 2; ++cc) {
                        ulonglong2 wg = WMXu[(col0 + cc) * 64 + l];
                        ulonglong2 wc = WMXu[(4 + col0 + cc) * 64 + l];
                        fma2(ag[cc][0], a.x, wg.x); fma2(ag[cc][1], a.y, wg.y);
                        fma2(ac[cc][0], a.x, wc.x); fma2(ac[cc][1], a.y, wc.y);
                    }
                }
            }
            __syncthreads();
            stage32(b0, vbase + 1024, Hh * 4, rs0, kk);   // Vb (K 256..511)
            cp_wait<1>(); __syncthreads();                // Va ready, rstd visible
            unsigned long long rstd2;
            {
                float rv = sm[OFF_RSTD + s * 32 + r];
                asm("mov.b64 %0, {%1, %1};" : "=l"(rstd2) : "f"(rv));
            }
#pragma unroll
            for (int half = 0; half < 2; ++half) {
                if (half == 1) { cp_wait<0>(); __syncthreads(); }
                const ulonglong2* sp = reinterpret_cast<const ulonglong2*>(
                                           half == 0 ? b1 : b0) + r * 64;
                int goff = half * 64;
#pragma unroll
                for (int j = 0; j < 8; ++j) {
                    int l = j * 8 + kpart;
                    ulonglong2 a = sp[l ^ sw];
                    a.x = mul2(a.x, rstd2); a.y = mul2(a.y, rstd2);
#pragma unroll
                    for (int cc = 0; cc < 2; ++cc) {
                        ulonglong2 wg = WMVu[(col0 + cc) * 128 + goff + l];
                        ulonglong2 wc = WMVu[(4 + col0 + cc) * 128 + goff + l];
                        fma2(ag[cc][0], a.x, wg.x); fma2(ag[cc][1], a.y, wg.y);
                        fma2(ac[cc][0], a.x, wc.x); fma2(ac[cc][1], a.y, wc.y);
                    }
                }
            }
            red4[tid] = make_float4(hsum(ag[0][0]) + hsum(ag[0][1]),
                                    hsum(ag[1][0]) + hsum(ag[1][1]),
                                    hsum(ac[0][0]) + hsum(ac[0][1]),
                                    hsum(ac[1][0]) + hsum(ac[1][1]));
            __syncthreads();
            if (owner) {
                float G[2] = {0.f, 0.f}, C[2] = {0.f, 0.f};
#pragma unroll
                for (int kp = 0; kp < 8; ++kp) {
                    float4 p = red4[kp * 64 + c2 * 32 + r];
                    G[0] += p.x; G[1] += p.y; C[0] += p.z; C[1] += p.w;
                }
                float mr = muv * rstdv;
                float2 zf, cf;
#pragma unroll
                for (int cc = 0; cc < 2; ++cc) {
                    float gv = G[cc] + sm[OFF_B + col0 + cc];
                    float cv = C[cc] + sm[OFF_B + 4 + col0 + cc];
                    if (t > 0) {
                        gv += sm[OFF_B + 28 + col0 + cc]
                              - mr * sm[OFF_B + 36 + col0 + cc];
                        cv += sm[OFF_B + 28 + 4 + col0 + cc]
                              - mr * sm[OFF_B + 36 + 4 + col0 + cc];
                    }
                    float sg = 1.f / (1.f + expf(-gv));
                    float zz = sg * tanhf(cv);
                    if (cc == 0) { zf.x = zz; cf.x = cv; }
                    else         { zf.y = zz; cf.y = cv; }
                }
                int grow = s * 32 + r;
                *reinterpret_cast<float2*>(&g_z[grow * Hh + cbase + col0])    = zf;
                *reinterpret_cast<float2*>(&g_core[grow * Hh + cbase + col0]) = cf;
            }
            cnt[s] += NCTA; bar_arrive(s);
        }

        // ======================= PHASE B+C (both streams) ===================
#pragma unroll
        for (int s = 0; s < 2; ++s) {
            float4* b0 = SB + (2 * s) * 2048;
            float4* b1 = SB + (2 * s + 1) * 2048;
            const char* cbase_g = (const char*)(g_core + (size_t)s * 32 * Hh);
            const char* zbase_g = (const char*)(g_z + (size_t)s * 32 * Hh);

            bar_wait(s, cnt[s]);
            if (bid == 0 && tid < 64) {                // zero LN accs parity par^1
                int pp = par ^ 1;
                if (tid < 32) g_rs[s * 64 + pp * 32 + tid] = 0.f;
                else          g_rq[s * 64 + pp * 32 + (tid - 32)] = 0.f;
            }
            stage32(b0, cbase_g, Hh * 4, rs0, kk);
            stage32(b1, cbase_g + 1024, Hh * 4, rs0, kk);

            unsigned long long at[2][2] = {};
            cp_wait<1>(); __syncthreads();
            {
                const ulonglong2* sp =
                    reinterpret_cast<const ulonglong2*>(b0) + r * 64;
#pragma unroll
                for (int j = 0; j < 8; ++j) {
                    int l = j * 8 + kpart;
                    ulonglong2 a = sp[l ^ sw];
#pragma unroll
                    for (int cc = 0; cc < 2; ++cc) {
                        ulonglong2 ww = WTu[(col0 + cc) * 128 + l];
                        fma2(at[cc][0], a.x, ww.x); fma2(at[cc][1], a.y, ww.y);
                    }
                }
            }
            __syncthreads();
            stage32(b0, zbase_g, Hh * 4, rs0, kk);
            cp_wait<1>(); __syncthreads();
            {
                const ulonglong2* sp =
                    reinterpret_cast<const ulonglong2*>(b1) + r * 64;
#pragma unroll
                for (int j = 0; j < 8; ++j) {
                    int l = j * 8 + kpart;
                    ulonglong2 a = sp[l ^ sw];
#pragma unroll
                    for (int cc = 0; cc < 2; ++cc) {
                        ulonglong2 ww = WTu[(col0 + cc) * 128 + 64 + l];
                        fma2(at[cc][0], a.x, ww.x); fma2(at[cc][1], a.y, ww.y);
                    }
                }
            }
            red2[tid] = make_float2(hsum(at[0][0]) + hsum(at[0][1]),
                                    hsum(at[1][0]) + hsum(at[1][1]));
            __syncthreads();
            stage32(b1, zbase_g + 1024, Hh * 4, rs0, kk);
            if (owner) {
                float Tq[2] = {0.f, 0.f};
#pragma unroll
                for (int kp = 0; kp < 8; ++kp) {
                    float2 p = red2[kp * 64 + c2 * 32 + r];
                    Tq[0] += p.x; Tq[1] += p.y;
                }
#pragma unroll
                for (int cc = 0; cc < 2; ++cc) {
                    float tl = Tq[cc] + sm[OFF_B + 8 + col0 + cc];
                    float spv = (tl > 20.f) ? tl : log1pf(expf(tl));
                    dtT[s][cc] = DTc / (spv + 1e-6f);
                }
            }
            unsigned long long af[2][2] = {};
            cp_wait<1>(); __syncthreads();
#pragma unroll
            for (int half = 0; half < 2; ++half) {
                if (half == 1) { cp_wait<0>(); __syncthreads(); }
                const ulonglong2* sp = reinterpret_cast<const ulonglong2*>(
                                           half == 0 ? b0 : b1) + r * 64;
                int goff = half * 64;
#pragma unroll
                for (int j = 0; j < 8; ++j) {
                    int l = j * 8 + kpart;
                    ulonglong2 a = sp[l ^ sw];
#pragma unroll
                    for (int cc = 0; cc < 2; ++cc) {
                        ulonglong2 ww = WF1u[(col0 + cc) * 128 + goff + l];
                        fma2(af[cc][0], a.x, ww.x); fma2(af[cc][1], a.y, ww.y);
                    }
                }
            }
            red2[tid] = make_float2(hsum(af[0][0]) + hsum(af[0][1]),
                                    hsum(af[1][0]) + hsum(af[1][1]));
            __syncthreads();
            if (owner) {
                float F[2] = {0.f, 0.f};
#pragma unroll
                for (int kp = 0; kp < 8; ++kp) {
                    float2 p = red2[kp * 64 + c2 * 32 + r];
                    F[0] += p.x; F[1] += p.y;
                }
                float2 a1v;
                float f0 = F[0] + sm[OFF_B + 12 + col0];
                float f1 = F[1] + sm[OFF_B + 12 + col0 + 1];
                a1v.x = f0 / (1.f + expf(-f0));
                a1v.y = f1 / (1.f + expf(-f1));
                *reinterpret_cast<float2*>(
                    &g_a1[(s * 32 + r) * Hh + cbase + col0]) = a1v;
            }
            cnt[s] += NCTA; bar_arrive(s);
        }

        // ======================= PHASE D (both streams) =====================
#pragma unroll
        for (int s = 0; s < 2; ++s) {
            float4* b0 = SB + (2 * s) * 2048;
            float4* b1 = SB + (2 * s + 1) * 2048;
            const char* abase = (const char*)(g_a1 + (size_t)s * 32 * Hh);

            bar_wait(s, cnt[s]);
            stage32(b0, abase, Hh * 4, rs0, kk);
            stage32(b1, abase + 1024, Hh * 4, rs0, kk);

            unsigned long long ao[2][2] = {};
            cp_wait<1>(); __syncthreads();
            {
                const ulonglong2* sp =
                    reinterpret_cast<const ulonglong2*>(b0) + r * 64;
#pragma unroll
                for (int j = 0; j < 8; ++j) {
                    int l = j * 8 + kpart;
                    ulonglong2 a = sp[l ^ sw];
#pragma unroll
                    for (int cc = 0; cc < 2; ++cc) {
                        ulonglong2 ww = WF2u[(col0 + cc) * 128 + l];
                        fma2(ao[cc][0], a.x, ww.x); fma2(ao[cc][1], a.y, ww.y);
                    }
                }
            }
            __syncthreads();
            if (t + 1 < Tt) {
                stage32(b0, (const char*)(x + (size_t)s * 32 * Tt * DIN
                                            + (size_t)(t + 1) * DIN),
                        (size_t)Tt * DIN * 4, rs0, kk);
                cp_wait<1>();
            } else {
                cp_wait<0>();
            }
            __syncthreads();
            {
                const ulonglong2* sp =
                    reinterpret_cast<const ulonglong2*>(b1) + r * 64;
#pragma unroll
                for (int j = 0; j < 8; ++j) {
                    int l = j * 8 + kpart;
                    ulonglong2 a = sp[l ^ sw];
#pragma unroll
                    for (int cc = 0; cc < 2; ++cc) {
                        ulonglong2 ww = WF2u[(col0 + cc) * 128 + 64 + l];
                        fma2(ao[cc][0], a.x, ww.x); fma2(ao[cc][1], a.y, ww.y);
                    }
                }
            }
            red2[tid] = make_float2(hsum(ao[0][0]) + hsum(ao[0][1]),
                                    hsum(ao[1][0]) + hsum(ao[1][1]));
            __syncthreads();
            if (owner) {
                float F[2] = {0.f, 0.f};
#pragma unroll
                for (int kp = 0; kp < 8; ++kp) {
                    float2 p = red2[kp * 64 + c2 * 32 + r];
                    F[0] += p.x; F[1] += p.y;
                }
                float2 vv;
                float ssum = 0.f, qsum = 0.f;
#pragma unroll
                for (int cc = 0; cc < 2; ++cc) {
                    float f = F[cc] + sm[OFF_B + 16 + col0 + cc];
                    float v = hprev[s][cc] + dtT[s][cc] * f;
                    vkeep[s][cc] = v;
                    if (cc == 0) vv.x = v; else vv.y = v;
                    ssum += v; qsum += v * v;
                }
                *reinterpret_cast<float2*>(
                    &g_v[(s * 32 + r) * Hh + cbase + col0]) = vv;
                atomicAdd(&g_rs[s * 64 + par * 32 + r], ssum);
                atomicAdd(&g_rq[s * 64 + par * 32 + r], qsum);
            }
            cnt[s] += NCTA; bar_arrive(s);
        }
    }

    // final output row (t = Tt-1) for both streams
#pragma unroll
    for (int s = 0; s < 2; ++s) {
        bar_wait(s, cnt[s]);
        if (owner) {
            int pp = (Tt - 1) & 1;
            float ssum = __ldcg(&g_rs[s * 64 + pp * 32 + r]);
            float qsum = __ldcg(&g_rq[s * 64 + pp * 32 + r]);
            float muv = ssum * (1.f / 512.f);
            float var = qsum * (1.f / 512.f) - muv * muv;
            float rstdv = rsqrtf(var + EPSc);
            float2 hn;
            hn.x = (vkeep[s][0] - muv) * rstdv * sm[OFF_B + 20 + col0]
                   + sm[OFF_B + 24 + col0];
            hn.y = (vkeep[s][1] - muv) * rstdv * sm[OFF_B + 20 + col0 + 1]
                   + sm[OFF_B + 24 + col0 + 1];
            *reinterpret_cast<float2*>(
                out + ((size_t)(s * 32 + r) * Tt + (Tt - 1)) * Hh
                    + cbase + col0) = hn;
        }
    }
}

extern "C" void kernel_launch(void* const* d_in, const int* in_sizes, int n_in,
                              void* d_out, int out_size) {
    const float* x     = (const float*)d_in[0];
    const float* Wm    = (const float*)d_in[1];
    const float* bm    = (const float*)d_in[2];
    const float* Wf1   = (const float*)d_in[3];
    const float* bf1   = (const float*)d_in[4];
    const float* Wf2   = (const float*)d_in[5];
    const float* bf2   = (const float*)d_in[6];
    const float* Wt    = (const float*)d_in[7];
    const float* bt    = (const float*)d_in[8];
    const float* gamma = (const float*)d_in[9];
    const float* beta  = (const float*)d_in[10];
    float* out = (float*)d_out;

    cudaFuncSetAttribute(ctlnn_main, cudaFuncAttributeMaxDynamicSharedMemorySize,
                         SMEM_FLOATS * sizeof(float));

    ctlnn_reset<<<64, 256>>>();
    ctlnn_main<<<NCTA, NTHR, SMEM_FLOATS * sizeof(float)>>>(
        x, Wm, bm, Wf1, bf1, Wf2, bf2, Wt, bt, gamma, beta, out);
}

// round 8
// speedup vs baseline: 1.3844x; 1.3844x over previous
#include <cuda_runtime.h>
#include <cmath>

// ---------------------------------------------------------------------------
// CTLNN persistent kernel, round 8.
// 128 CTAs = 2 row-halves x 64 col-groups. Each CTA: 32 batch rows, 8 H-cols
// (16 A-cols: 8 gate + 8 core). 512 threads = (r:32, ch:2, kp:8); thread
// computes 4 cols over a K/8 slice (ch selects which 4 of the CTA's 8).
// Halves the L2 activation broadcast traffic vs the 64-row/4-col layout.
// LayerNorm folded into phase A (gamma into Wm h-rows, rstd scales staged v,
// beta/mu per-column constants). cp.async double-buffered staging, FFMA2
// inner loops, 3 grid barriers per step.
// ---------------------------------------------------------------------------

namespace {
constexpr int Tt   = 1024;
constexpr int DIN  = 256;
constexpr int Hh   = 512;
constexpr int NCTA = 128;
constexpr int NTHR = 512;
constexpr float DTc  = 0.01f;
constexpr float EPSc = 1e-5f;

// SMEM float offsets
constexpr int OFF_WMX   = 0;        // 16 x 256 (x-rows of Wm) [c16][k]
constexpr int OFF_WMV   = 4096;     // 16 x 512 (h-rows, gamma-folded)
constexpr int OFF_WT    = 12288;    // 8 x 512
constexpr int OFF_WF1   = 16384;
constexpr int OFF_WF2   = 20480;
constexpr int OFF_STAGE = 24576;    // 2 buffers x (32 rows x 64 granules) f4
constexpr int OFF_RED   = 40960;    // 512 x 8 floats
constexpr int OFF_B     = 45056;    // 88 consts
constexpr int OFF_RSTD  = 45144;    // 32
constexpr int SMEM_FLOATS = 45184;  // ~180.7 KB
// OFF_B: 0 bmg[8] 8 bmc[8] 16 bt[8] 24 bf1[8] 32 bf2[8] 40 gam[8] 48 bet[8]
//        56 Bsum[16] (g0..7,core0..7)  72 Gsum[16]
}

// Cross-CTA state
__device__ unsigned g_bar;
__device__ float g_rs[128], g_rq[128];     // [par][globalRow]
__device__ float g_v[64 * Hh];
__device__ float g_core[64 * Hh];
__device__ float g_z[64 * Hh];
__device__ float g_a1[64 * Hh];

__global__ void ctlnn_reset() {
    int i = blockIdx.x * blockDim.x + threadIdx.x;
    if (i == 0) g_bar = 0u;
    if (i < 128) { g_rs[i] = 0.f; g_rq[i] = 0.f; }
    for (int k = i; k < 64 * Hh; k += gridDim.x * blockDim.x) g_v[k] = 0.f;
}

// ---- helpers --------------------------------------------------------------
__device__ __forceinline__ void cp16(float4* dst, const void* src) {
    unsigned s = (unsigned)__cvta_generic_to_shared(dst);
    asm volatile("cp.async.cg.shared.global [%0], [%1], 16;" :: "r"(s), "l"(src));
}
__device__ __forceinline__ void cp_commit() {
    asm volatile("cp.async.commit_group;" ::: "memory");
}
template <int N>
__device__ __forceinline__ void cp_wait() {
    asm volatile("cp.async.wait_group %0;" :: "n"(N) : "memory");
}
__device__ __forceinline__ void fma2(unsigned long long& d,
                                     unsigned long long a, unsigned long long b) {
    asm volatile("fma.rn.f32x2 %0, %1, %2, %3;" : "=l"(d) : "l"(a), "l"(b), "l"(d));
}
__device__ __forceinline__ unsigned long long mul2(unsigned long long a,
                                                   unsigned long long b) {
    unsigned long long d;
    asm("mul.rn.f32x2 %0, %1, %2;" : "=l"(d) : "l"(a), "l"(b));
    return d;
}
__device__ __forceinline__ float hsum(unsigned long long u) {
    float lo, hi;
    asm("mov.b64 {%0,%1}, %2;" : "=f"(lo), "=f"(hi) : "l"(u));
    return lo + hi;
}

__device__ __forceinline__ void grid_bar(unsigned target) {
    __threadfence();
    __syncthreads();
    if (threadIdx.x == 0) {
        atomicAdd(&g_bar, 1u);
        unsigned v;
        do {
            asm volatile("ld.global.acquire.gpu.u32 %0, [%1];"
                         : "=r"(v) : "l"(&g_bar));
        } while (v < target);
    }
    __syncthreads();
}

// Stage one 32-row x 64-granule(16B) chunk into SMEM with XOR swizzle.
__device__ __forceinline__ void stage32(float4* __restrict__ dst,
                                        const char* __restrict__ gbase,
                                        size_t rstrideB, int rs0, int kk) {
#pragma unroll
    for (int i = 0; i < 4; ++i) {
        int rs = rs0 + i * 8;
        cp16(dst + rs * 64 + (kk ^ (rs & 7)),
             gbase + (size_t)rs * rstrideB + kk * 16);
    }
    cp_commit();
}

// Phase-A x-dot: 8 outputs (4 g + 4 core), weight col stride 64 granules.
__device__ __forceinline__ void dotAx(const ulonglong2* __restrict__ sp, int sw,
                                      int kp,
                                      const ulonglong2* __restrict__ wg,
                                      const ulonglong2* __restrict__ wc,
                                      unsigned long long ag[4][2],
                                      unsigned long long ac[4][2]) {
#pragma unroll
    for (int j = 0; j < 8; ++j) {
        int l = j * 8 + kp;
        ulonglong2 a = sp[l ^ sw];
#pragma unroll
        for (int cc = 0; cc < 4; ++cc) {
            ulonglong2 g = wg[cc * 64 + l];
            ulonglong2 c = wc[cc * 64 + l];
            fma2(ag[cc][0], a.x, g.x); fma2(ag[cc][1], a.y, g.y);
            fma2(ac[cc][0], a.x, c.x); fma2(ac[cc][1], a.y, c.y);
        }
    }
}
// Phase-A v-dot (rstd-scaled), weight col stride 128 granules.
__device__ __forceinline__ void dotAv(const ulonglong2* __restrict__ sp, int sw,
                                      int kp, int goff,
                                      unsigned long long rstd2,
                                      const ulonglong2* __restrict__ wg,
                                      const ulonglong2* __restrict__ wc,
                                      unsigned long long ag[4][2],
                                      unsigned long long ac[4][2]) {
#pragma unroll
    for (int j = 0; j < 8; ++j) {
        int l = j * 8 + kp;
        ulonglong2 a = sp[l ^ sw];
        a.x = mul2(a.x, rstd2); a.y = mul2(a.y, rstd2);
        int wi = goff + l;
#pragma unroll
        for (int cc = 0; cc < 4; ++cc) {
            ulonglong2 g = wg[cc * 128 + wi];
            ulonglong2 c = wc[cc * 128 + wi];
            fma2(ag[cc][0], a.x, g.x); fma2(ag[cc][1], a.y, g.y);
            fma2(ac[cc][0], a.x, c.x); fma2(ac[cc][1], a.y, c.y);
        }
    }
}
// Generic 4-col dot (phases B/C/D), weight col stride 128 granules.
__device__ __forceinline__ void dot4(const ulonglong2* __restrict__ sp, int sw,
                                     int kp, int goff,
                                     const ulonglong2* __restrict__ w,
                                     unsigned long long acc[4][2]) {
#pragma unroll
    for (int j = 0; j < 8; ++j) {
        int l = j * 8 + kp;
        ulonglong2 a = sp[l ^ sw];
        int wi = goff + l;
#pragma unroll
        for (int cc = 0; cc < 4; ++cc) {
            ulonglong2 ww = w[cc * 128 + wi];
            fma2(acc[cc][0], a.x, ww.x);
            fma2(acc[cc][1], a.y, ww.y);
        }
    }
}

__global__ void __launch_bounds__(NTHR, 1)
ctlnn_main(const float* __restrict__ x,
           const float* __restrict__ Wm,  const float* __restrict__ bm,
           const float* __restrict__ Wf1, const float* __restrict__ bf1,
           const float* __restrict__ Wf2, const float* __restrict__ bf2,
           const float* __restrict__ Wt,  const float* __restrict__ bt,
           const float* __restrict__ gamma, const float* __restrict__ beta,
           float* __restrict__ out) {
    extern __shared__ __align__(16) float sm[];
    const int tid = threadIdx.x;
    const int bid = blockIdx.x;
    const int rh  = bid >> 6;        // row half: 0 -> rows 0..31, 1 -> 32..63
    const int cg  = bid & 63;        // column group
    const int cbase = cg * 8;        // first owned H-column

    // ---- one-time weight slice load ----
    for (int idx = tid; idx < 16 * 256; idx += NTHR) {   // Wm x-rows
        int c = idx >> 8, k = idx & 255;
        int srccol = (c < 8) ? (cbase + c) : (512 + cbase + (c - 8));
        sm[OFF_WMX + idx] = Wm[k * 1024 + srccol];
    }
    for (int idx = tid; idx < 16 * 512; idx += NTHR) {   // Wm h-rows * gamma
        int c = idx >> 9, k = idx & 511;
        int srccol = (c < 8) ? (cbase + c) : (512 + cbase + (c - 8));
        sm[OFF_WMV + idx] = Wm[(256 + k) * 1024 + srccol] * gamma[k];
    }
    for (int idx = tid; idx < 8 * 512; idx += NTHR) {
        int c = idx >> 9, k = idx & 511;
        int col = cbase + c;
        sm[OFF_WT  + idx] = Wt [k * 512 + col];
        sm[OFF_WF1 + idx] = Wf1[k * 512 + col];
        sm[OFF_WF2 + idx] = Wf2[k * 512 + col];
    }
    if (tid < 8) {
        int col = cbase + tid;
        sm[OFF_B +  0 + tid] = bm[col];
        sm[OFF_B +  8 + tid] = bm[512 + col];
        sm[OFF_B + 16 + tid] = bt[col];
        sm[OFF_B + 24 + tid] = bf1[col];
        sm[OFF_B + 32 + tid] = bf2[col];
        sm[OFF_B + 40 + tid] = gamma[col];
        sm[OFF_B + 48 + tid] = beta[col];
    }
    {   // per-column LN-fold constants Bsum/Gsum (16 A-cols)
        int w = tid >> 5, lane = tid & 31;
        if (w < 16) {
            int srccol = (w < 8) ? (cbase + w) : (512 + cbase + (w - 8));
            float sb = 0.f, sg = 0.f;
            for (int k = lane; k < 512; k += 32) {
                float wv = Wm[(256 + k) * 1024 + srccol];
                sb += beta[k] * wv;
                sg += gamma[k] * wv;
            }
#pragma unroll
            for (int o = 16; o; o >>= 1) {
                sb += __shfl_xor_sync(~0u, sb, o);
                sg += __shfl_xor_sync(~0u, sg, o);
            }
            if (lane == 0) { sm[OFF_B + 56 + w] = sb; sm[OFF_B + 72 + w] = sg; }
        }
    }
    __syncthreads();

    float4* bufA = reinterpret_cast<float4*>(sm + OFF_STAGE);
    float4* bufB = bufA + 32 * 64;
    float4* red4 = reinterpret_cast<float4*>(sm + OFF_RED);

    const int r   = tid & 31;         // local row
    const int ch  = (tid >> 5) & 1;   // column half (which 4 of the 8)
    const int kp  = tid >> 6;         // K-eighth
    const int sw  = r & 7;
    const int rs0 = tid >> 6;         // staging row phase
    const int kk  = tid & 63;         // staging granule
    const int gR  = rh * 32 + r;      // global batch row
    const int colw = ch * 4;          // first weight col within CTA
    const bool owner = (kp == 0);

    const ulonglong2* WMXg = reinterpret_cast<const ulonglong2*>(sm + OFF_WMX) + colw * 64;
    const ulonglong2* WMXc = reinterpret_cast<const ulonglong2*>(sm + OFF_WMX) + (8 + colw) * 64;
    const ulonglong2* WMVg = reinterpret_cast<const ulonglong2*>(sm + OFF_WMV) + colw * 128;
    const ulonglong2* WMVc = reinterpret_cast<const ulonglong2*>(sm + OFF_WMV) + (8 + colw) * 128;
    const ulonglong2* WTu  = reinterpret_cast<const ulonglong2*>(sm + OFF_WT)  + colw * 128;
    const ulonglong2* WF1u = reinterpret_cast<const ulonglong2*>(sm + OFF_WF1) + colw * 128;
    const ulonglong2* WF2u = reinterpret_cast<const ulonglong2*>(sm + OFF_WF2) + colw * 128;

    const char* xbase    = (const char*)(x + (size_t)rh * 32 * Tt * DIN);
    const char* vbase    = (const char*)(g_v    + (size_t)rh * 32 * Hh);
    const char* corebase = (const char*)(g_core + (size_t)rh * 32 * Hh);
    const char* zbase    = (const char*)(g_z    + (size_t)rh * 32 * Hh);
    const char* abase    = (const char*)(g_a1   + (size_t)rh * 32 * Hh);

    float hprev[4] = {0.f, 0.f, 0.f, 0.f};
    float dtT[4]   = {0.f, 0.f, 0.f, 0.f};
    float vkeep[4] = {0.f, 0.f, 0.f, 0.f};
    unsigned bar_t = 0;

    // prefetch x(t=0) into bufA (1 group pending at loop entry)
    stage32(bufA, xbase, (size_t)Tt * DIN * 4, rs0, kk);

    for (int t = 0; t < Tt; ++t) {
        const int par = t & 1;

        // ============ PHASE A: mapped = [x_t, h] @ Wm (LN folded) ==========
        stage32(bufB, vbase, Hh * 4, rs0, kk);              // v0 -> B
        float muv = 0.f, rstdv = 0.f;
        if (owner) {
            if (t > 0) {   // finalize step t-1: LN of vkeep, write out
                int pp = (t - 1) & 1;
                float s = __ldcg(&g_rs[pp * 64 + gR]);
                float q = __ldcg(&g_rq[pp * 64 + gR]);
                muv = s * (1.f / 512.f);
                float var = q * (1.f / 512.f) - muv * muv;
                rstdv = rsqrtf(var + EPSc);
                float4 hn;
                hn.x = (vkeep[0] - muv) * rstdv * sm[OFF_B + 40 + colw + 0] + sm[OFF_B + 48 + colw + 0];
                hn.y = (vkeep[1] - muv) * rstdv * sm[OFF_B + 40 + colw + 1] + sm[OFF_B + 48 + colw + 1];
                hn.z = (vkeep[2] - muv) * rstdv * sm[OFF_B + 40 + colw + 2] + sm[OFF_B + 48 + colw + 2];
                hn.w = (vkeep[3] - muv) * rstdv * sm[OFF_B + 40 + colw + 3] + sm[OFF_B + 48 + colw + 3];
                *reinterpret_cast<float4*>(
                    out + ((size_t)gR * Tt + (t - 1)) * Hh + cbase + colw) = hn;
                hprev[0] = hn.x; hprev[1] = hn.y; hprev[2] = hn.z; hprev[3] = hn.w;
            }
            if (ch == 0) sm[OFF_RSTD + r] = rstdv;   // 0 at t=0
        }
        unsigned long long ag[4][2] = {}, ac[4][2] = {};
        cp_wait<1>(); __syncthreads();                      // x ready (bufA)
        dotAx(reinterpret_cast<const ulonglong2*>(bufA) + r * 64, sw, kp,
              WMXg, WMXc, ag, ac);
        __syncthreads();
        stage32(bufA, vbase + 1024, Hh * 4, rs0, kk);       // v1 -> A
        unsigned long long rstd2;
        {
            float rv = sm[OFF_RSTD + r];
            asm("mov.b64 %0, {%1, %1};" : "=l"(rstd2) : "f"(rv));
        }
        cp_wait<1>(); __syncthreads();                      // v0 ready
        dotAv(reinterpret_cast<const ulonglong2*>(bufB) + r * 64, sw, kp, 0,
              rstd2, WMVg, WMVc, ag, ac);
        cp_wait<0>(); __syncthreads();                      // v1 ready
        dotAv(reinterpret_cast<const ulonglong2*>(bufA) + r * 64, sw, kp, 64,
              rstd2, WMVg, WMVc, ag, ac);
        red4[tid * 2 + 0] = make_float4(hsum(ag[0][0]) + hsum(ag[0][1]),
                                        hsum(ag[1][0]) + hsum(ag[1][1]),
                                        hsum(ag[2][0]) + hsum(ag[2][1]),
                                        hsum(ag[3][0]) + hsum(ag[3][1]));
        red4[tid * 2 + 1] = make_float4(hsum(ac[0][0]) + hsum(ac[0][1]),
                                        hsum(ac[1][0]) + hsum(ac[1][1]),
                                        hsum(ac[2][0]) + hsum(ac[2][1]),
                                        hsum(ac[3][0]) + hsum(ac[3][1]));
        __syncthreads();
        if (owner) {
            float G[4] = {0, 0, 0, 0}, C[4] = {0, 0, 0, 0};
#pragma unroll
            for (int kpp = 0; kpp < 8; ++kpp) {
                float4 pg = red4[(kpp * 64 + ch * 32 + r) * 2 + 0];
                float4 pc = red4[(kpp * 64 + ch * 32 + r) * 2 + 1];
                G[0] += pg.x; G[1] += pg.y; G[2] += pg.z; G[3] += pg.w;
                C[0] += pc.x; C[1] += pc.y; C[2] += pc.z; C[3] += pc.w;
            }
            float mr = muv * rstdv;
            float4 zf, cf;
            float* zp = &zf.x;
            float* cpp = &cf.x;
#pragma unroll
            for (int cc = 0; cc < 4; ++cc) {
                float gv = G[cc] + sm[OFF_B + colw + cc];
                float cv = C[cc] + sm[OFF_B + 8 + colw + cc];
                if (t > 0) {
                    gv += sm[OFF_B + 56 + colw + cc]     - mr * sm[OFF_B + 72 + colw + cc];
                    cv += sm[OFF_B + 56 + 8 + colw + cc] - mr * sm[OFF_B + 72 + 8 + colw + cc];
                }
                float sg = 1.f / (1.f + expf(-gv));
                cpp[cc] = cv;
                zp[cc]  = sg * tanhf(cv);
            }
            *reinterpret_cast<float4*>(&g_z[gR * Hh + cbase + colw])    = zf;
            *reinterpret_cast<float4*>(&g_core[gR * Hh + cbase + colw]) = cf;
        }
        bar_t += NCTA; grid_bar(bar_t);
        if (bid == 0 && tid >= 64 && tid < 192) {   // zero LN accs parity par^1
            int i = tid - 64;
            if (i < 64) g_rs[(par ^ 1) * 64 + i] = 0.f;
            else        g_rq[(par ^ 1) * 64 + (i - 64)] = 0.f;
        }

        // ===== PHASE B: tau = softplus(core@Wt+bt); PHASE C: a1 ============
        stage32(bufA, corebase,        Hh * 4, rs0, kk);
        stage32(bufB, corebase + 1024, Hh * 4, rs0, kk);
        unsigned long long at[4][2] = {};
        cp_wait<1>(); __syncthreads();                      // core0 ready
        dot4(reinterpret_cast<const ulonglong2*>(bufA) + r * 64, sw, kp, 0,
             WTu, at);
        __syncthreads();
        stage32(bufA, zbase, Hh * 4, rs0, kk);              // z0 -> A
        cp_wait<1>(); __syncthreads();                      // core1 ready
        dot4(reinterpret_cast<const ulonglong2*>(bufB) + r * 64, sw, kp, 64,
             WTu, at);
        red4[tid] = make_float4(hsum(at[0][0]) + hsum(at[0][1]),
                                hsum(at[1][0]) + hsum(at[1][1]),
                                hsum(at[2][0]) + hsum(at[2][1]),
                                hsum(at[3][0]) + hsum(at[3][1]));
        __syncthreads();
        stage32(bufB, zbase + 1024, Hh * 4, rs0, kk);       // z1 -> B
        if (owner) {
            float Tq[4] = {0, 0, 0, 0};
#pragma unroll
            for (int kpp = 0; kpp < 8; ++kpp) {
                float4 p = red4[kpp * 64 + ch * 32 + r];
                Tq[0] += p.x; Tq[1] += p.y; Tq[2] += p.z; Tq[3] += p.w;
            }
#pragma unroll
            for (int cc = 0; cc < 4; ++cc) {
                float tl = Tq[cc] + sm[OFF_B + 16 + colw + cc];
                float spv = (tl > 20.f) ? tl : log1pf(expf(tl));
                dtT[cc] = DTc / (spv + 1e-6f);
            }
        }
        unsigned long long af[4][2] = {};
        cp_wait<1>(); __syncthreads();                      // z0 ready
        dot4(reinterpret_cast<const ulonglong2*>(bufA) + r * 64, sw, kp, 0,
             WF1u, af);
        cp_wait<0>(); __syncthreads();                      // z1 ready
        dot4(reinterpret_cast<const ulonglong2*>(bufB) + r * 64, sw, kp, 64,
             WF1u, af);
        red4[tid] = make_float4(hsum(af[0][0]) + hsum(af[0][1]),
                                hsum(af[1][0]) + hsum(af[1][1]),
                                hsum(af[2][0]) + hsum(af[2][1]),
                                hsum(af[3][0]) + hsum(af[3][1]));
        __syncthreads();
        if (owner) {
            float F[4] = {0, 0, 0, 0};
#pragma unroll
            for (int kpp = 0; kpp < 8; ++kpp) {
                float4 p = red4[kpp * 64 + ch * 32 + r];
                F[0] += p.x; F[1] += p.y; F[2] += p.z; F[3] += p.w;
            }
            float4 a1v;
            float* ap = &a1v.x;
#pragma unroll
            for (int cc = 0; cc < 4; ++cc) {
                float f1 = F[cc] + sm[OFF_B + 24 + colw + cc];
                ap[cc] = f1 / (1.f + expf(-f1));
            }
            *reinterpret_cast<float4*>(&g_a1[gR * Hh + cbase + colw]) = a1v;
        }
        bar_t += NCTA; grid_bar(bar_t);

        // ===== PHASE D: f = a1@Wf2 + bf2; v = h + dt/tau * f ===============
        stage32(bufA, abase,        Hh * 4, rs0, kk);
        stage32(bufB, abase + 1024, Hh * 4, rs0, kk);
        unsigned long long ao[4][2] = {};
        cp_wait<1>(); __syncthreads();                      // a1_0 ready
        dot4(reinterpret_cast<const ulonglong2*>(bufA) + r * 64, sw, kp, 0,
             WF2u, ao);
        __syncthreads();
        if (t + 1 < Tt) {                                   // x(t+1) -> A
            stage32(bufA, xbase + (size_t)(t + 1) * DIN * 4,
                    (size_t)Tt * DIN * 4, rs0, kk);
            cp_wait<1>();
        } else {
            cp_wait<0>();
        }
        __syncthreads();                                    // a1_1 ready
        dot4(reinterpret_cast<const ulonglong2*>(bufB) + r * 64, sw, kp, 64,
             WF2u, ao);
        red4[tid] = make_float4(hsum(ao[0][0]) + hsum(ao[0][1]),
                                hsum(ao[1][0]) + hsum(ao[1][1]),
                                hsum(ao[2][0]) + hsum(ao[2][1]),
                                hsum(ao[3][0]) + hsum(ao[3][1]));
        __syncthreads();
        if (owner) {
            float F[4] = {0, 0, 0, 0};
#pragma unroll
            for (int kpp = 0; kpp < 8; ++kpp) {
                float4 p = red4[kpp * 64 + ch * 32 + r];
                F[0] += p.x; F[1] += p.y; F[2] += p.z; F[3] += p.w;
            }
            float ssum = 0.f, qsum = 0.f;
            float4 vv;
            float* vp = &vv.x;
#pragma unroll
            for (int cc = 0; cc < 4; ++cc) {
                float f = F[cc] + sm[OFF_B + 32 + colw + cc];
                float v = hprev[cc] + dtT[cc] * f;
                vkeep[cc] = v;
                vp[cc] = v;
                ssum += v; qsum += v * v;
            }
            *reinterpret_cast<float4*>(&g_v[gR * Hh + cbase + colw]) = vv;
            atomicAdd(&g_rs[par * 64 + gR], ssum);
            atomicAdd(&g_rq[par * 64 + gR], qsum);
        }
        bar_t += NCTA; grid_bar(bar_t);
    }

    // final output row (t = Tt-1)
    if (owner) {
        int pp = (Tt - 1) & 1;
        float s = __ldcg(&g_rs[pp * 64 + gR]);
        float q = __ldcg(&g_rq[pp * 64 + gR]);
        float muv = s * (1.f / 512.f);
        float var = q * (1.f / 512.f) - muv * muv;
        float rstdv = rsqrtf(var + EPSc);
        float4 hn;
        hn.x = (vkeep[0] - muv) * rstdv * sm[OFF_B + 40 + colw + 0] + sm[OFF_B + 48 + colw + 0];
        hn.y = (vkeep[1] - muv) * rstdv * sm[OFF_B + 40 + colw + 1] + sm[OFF_B + 48 + colw + 1];
        hn.z = (vkeep[2] - muv) * rstdv * sm[OFF_B + 40 + colw + 2] + sm[OFF_B + 48 + colw + 2];
        hn.w = (vkeep[3] - muv) * rstdv * sm[OFF_B + 40 + colw + 3] + sm[OFF_B + 48 + colw + 3];
        *reinterpret_cast<float4*>(
            out + ((size_t)gR * Tt + (Tt - 1)) * Hh + cbase + colw) = hn;
    }
}

extern "C" void kernel_launch(void* const* d_in, const int* in_sizes, int n_in,
                              void* d_out, int out_size) {
    const float* x     = (const float*)d_in[0];
    const float* Wm    = (const float*)d_in[1];
    const float* bm    = (const float*)d_in[2];
    const float* Wf1   = (const float*)d_in[3];
    const float* bf1   = (const float*)d_in[4];
    const float* Wf2   = (const float*)d_in[5];
    const float* bf2   = (const float*)d_in[6];
    const float* Wt    = (const float*)d_in[7];
    const float* bt    = (const float*)d_in[8];
    const float* gamma = (const float*)d_in[9];
    const float* beta  = (const float*)d_in[10];
    float* out = (float*)d_out;

    cudaFuncSetAttribute(ctlnn_main, cudaFuncAttributeMaxDynamicSharedMemorySize,
                         SMEM_FLOATS * sizeof(float));

    ctlnn_reset<<<64, 256>>>();
    ctlnn_main<<<NCTA, NTHR, SMEM_FLOATS * sizeof(float)>>>(
        x, Wm, bm, Wf1, bf1, Wf2, bf2, Wt, bt, gamma, beta, out);
}